// round 8
// baseline (speedup 1.0000x reference)
#include <cuda_runtime.h>
#include <cuda_fp16.h>
#include <cstdint>

// Conditional_encoding: B=1024, T=256, V=32004, D=50, H=64
// Stage 1: GX[layer][v][256] = Wih@emb[v] + bih + bhh (token gate table, L2-resident).
// Stage 2: 147 CTAs x 512 threads, NB=7. Recurrence h@Whh^T on tensor cores,
//   m16n8k16 fp16 hi/lo split (3 passes, fp32-accurate).
//   NEW: warp w owns hidden dims 4w..4w+3 across ALL 4 gates (n-tile0 = {i,f} rows,
//   n-tile1 = {g,o} rows), so the LSTM cell update happens inside the MMA warp via
//   8 shuffles. h double-buffered in smem -> ONE barrier per step.

typedef unsigned long long ull;

#define NB   7
#define TPB  512
#define GRID 147
#define VOC  32004

__device__ float GXT[2][(size_t)VOC * 256];

__device__ __forceinline__ ull ffma2(ull a, ull b, ull c) {
    ull d;
    asm("fma.rn.f32x2 %0, %1, %2, %3;" : "=l"(d) : "l"(a), "l"(b), "l"(c));
    return d;
}
__device__ __forceinline__ float lo32(ull v) { return __uint_as_float((unsigned)v); }
__device__ __forceinline__ float hi32(ull v) { return __uint_as_float((unsigned)(v >> 32)); }
__device__ __forceinline__ float tanhap(float x) {
    float y;
    asm("tanh.approx.f32 %0, %1;" : "=f"(y) : "f"(x));
    return y;
}
__device__ __forceinline__ float sigm(float x) { return 0.5f * tanhap(0.5f * x) + 0.5f; }

__device__ __forceinline__ void mma16816(float& c0, float& c1, float& c2, float& c3,
                                         unsigned a0, unsigned a1, unsigned a2, unsigned a3,
                                         unsigned b0, unsigned b1) {
    asm volatile("mma.sync.aligned.m16n8k16.row.col.f32.f16.f16.f32 "
                 "{%0,%1,%2,%3}, {%4,%5,%6,%7}, {%8,%9}, {%0,%1,%2,%3};"
                 : "+f"(c0), "+f"(c1), "+f"(c2), "+f"(c3)
                 : "r"(a0), "r"(a1), "r"(a2), "r"(a3), "r"(b0), "r"(b1));
}
__device__ __forceinline__ unsigned h2u(__half2 h) { return *reinterpret_cast<unsigned*>(&h); }

// ---------------- stage 1: vocab gate-table precompute (4 tokens / iter) ----------------
#define PCT 4
#define PCI 14
#define PCC (PCT * PCI)
#define PCG ((VOC + PCC - 1) / PCC)

__global__ void __launch_bounds__(256)
precompute_gx(const float* __restrict__ emb,
              const float* __restrict__ Wih1, const float* __restrict__ bih1,
              const float* __restrict__ bhh1,
              const float* __restrict__ Wih2, const float* __restrict__ bih2,
              const float* __restrict__ bhh2)
{
    const int layer = blockIdx.y;
    const float* __restrict__ Wih = layer ? Wih2 : Wih1;
    const float* __restrict__ bi  = layer ? bih2 : bih1;
    const float* __restrict__ bh  = layer ? bhh2 : bhh1;
    float* __restrict__ GX = GXT[layer];

    const int tid = threadIdx.x;
    ull wih[25];
    const ull* wr = reinterpret_cast<const ull*>(Wih + tid * 50);
    #pragma unroll
    for (int k = 0; k < 25; k++) wih[k] = wr[k];
    const float bsum = bi[tid] + bh[tid];

    __shared__ __align__(16) float xb[2][PCT][52];
    const int v0 = blockIdx.x * PCC;
    const int lt = tid / 50, ld = tid % 50;
    const bool lp = tid < PCT * 50;

    if (lp) {
        int v = min(v0 + lt, VOC - 1);
        xb[0][lt][ld] = __ldg(&emb[(size_t)v * 50 + ld]);
    }
    __syncthreads();

    for (int it = 0; it < PCI; it++) {
        const int cur = it & 1;
        const int vb = v0 + it * PCT;
        float pf = 0.f;
        if (lp && it + 1 < PCI) {
            int v = min(vb + PCT + lt, VOC - 1);
            pf = __ldg(&emb[(size_t)v * 50 + ld]);
        }
        ull acc[PCT] = {0ull, 0ull, 0ull, 0ull};
        #pragma unroll
        for (int k = 0; k < 25; k++) {
            #pragma unroll
            for (int t = 0; t < PCT; t++)
                acc[t] = ffma2(wih[k], *reinterpret_cast<const ull*>(&xb[cur][t][k * 2]), acc[t]);
        }
        #pragma unroll
        for (int t = 0; t < PCT; t++) {
            int v = vb + t;
            if (v < VOC) GX[(size_t)v * 256 + tid] = (lo32(acc[t]) + hi32(acc[t])) + bsum;
        }
        if (lp && it + 1 < PCI) xb[cur ^ 1][lt][ld] = pf;
        __syncthreads();
    }
}

// ---------------- stage 2: fused recurrence on tensor cores ----------------
#define HPS 72    // h row stride in halves (conflict-free A-frag LDS)

struct SmemT {
    __half hhi[2][NB][HPS];    // double-buffered packed fp16 hi of h
    __half hlo[2][NB][HPS];    // double-buffered packed fp16 lo of h
    float  gh[NB][64];
    float  gc[NB][64];
    float  f1[NB][128];
    int    sidx[NB][256];
};

__device__ __forceinline__ void run_lstm(
    int warp, int lane, int grp, int tig, bool act, int hd, int myg,
    const float* __restrict__ gx, const float* __restrict__ Whh,
    SmemT* sm, float& c)
{
    // ---- B fragments: warp w owns Whh rows {g*64 + 4w + d : g in 0..3, d in 0..3}.
    // ntile0 -> gates i,f ; ntile1 -> gates g,o.  n-within-tile = grp.
    unsigned bhf[2][4][2], blf[2][4][2];
    #pragma unroll
    for (int nt = 0; nt < 2; nt++) {
        const int row = nt * 128 + (grp >> 2) * 64 + warp * 4 + (grp & 3);
        #pragma unroll
        for (int kt = 0; kt < 4; kt++) {
            int k = kt * 16 + tig * 2;
            float2 w0 = *reinterpret_cast<const float2*>(&Whh[row * 64 + k]);
            float2 w1 = *reinterpret_cast<const float2*>(&Whh[row * 64 + k + 8]);
            __half2 h0 = __floats2half2_rn(w0.x, w0.y);
            __half2 h1 = __floats2half2_rn(w1.x, w1.y);
            float2 r0 = __half22float2(h0), r1 = __half22float2(h1);
            __half2 l0 = __floats2half2_rn(w0.x - r0.x, w0.y - r0.y);
            __half2 l1 = __floats2half2_rn(w1.x - r1.x, w1.y - r1.y);
            bhf[nt][kt][0] = h2u(h0); bhf[nt][kt][1] = h2u(h1);
            blf[nt][kt][0] = h2u(l0); blf[nt][kt][1] = h2u(l1);
        }
    }

    const int j = grp;                       // batch owned by this lane group
    // current-step gx gate values
    float gi = 0.f, gf = 0.f, gg = 0.f, go = 0.f;
    if (act) {
        const float* p = gx + (size_t)sm->sidx[j][0] * 256 + hd;
        gi = __ldg(p); gf = __ldg(p + 64); gg = __ldg(p + 128); go = __ldg(p + 192);
    }

    for (int step = 0; step < 256; step++) {
        const int cur = step & 1;

        // ---- A fragments from packed h (broadcast LDS; rows >= 7 zero) ----
        unsigned ah[4][2], al[4][2];
        if (grp < NB) {
            #pragma unroll
            for (int kt = 0; kt < 4; kt++) {
                int off = kt * 16 + tig * 2;
                ah[kt][0] = *reinterpret_cast<const unsigned*>(&sm->hhi[cur][grp][off]);
                ah[kt][1] = *reinterpret_cast<const unsigned*>(&sm->hhi[cur][grp][off + 8]);
                al[kt][0] = *reinterpret_cast<const unsigned*>(&sm->hlo[cur][grp][off]);
                al[kt][1] = *reinterpret_cast<const unsigned*>(&sm->hlo[cur][grp][off + 8]);
            }
        } else {
            #pragma unroll
            for (int kt = 0; kt < 4; kt++) {
                ah[kt][0] = ah[kt][1] = 0u; al[kt][0] = al[kt][1] = 0u;
            }
        }

        // ---- prefetch next step's gx (L2 table) ----
        float n0 = 0.f, n1 = 0.f, n2 = 0.f, n3 = 0.f;
        if (act && step < 255) {
            const float* p = gx + (size_t)sm->sidx[j][step + 1] * 256 + hd;
            n0 = __ldg(p); n1 = __ldg(p + 64); n2 = __ldg(p + 128); n3 = __ldg(p + 192);
        }

        // ---- 24 HMMA: 2 ntiles x 2 k-half chains x 3 precision passes ----
        float cA0 = 0.f, cA1 = 0.f, cA2 = 0.f, cA3 = 0.f;
        float cB0 = 0.f, cB1 = 0.f, cB2 = 0.f, cB3 = 0.f;
        float cC0 = 0.f, cC1 = 0.f, cC2 = 0.f, cC3 = 0.f;
        float cD0 = 0.f, cD1 = 0.f, cD2 = 0.f, cD3 = 0.f;
        #pragma unroll
        for (int kh = 0; kh < 2; kh++) {
            float &x0 = kh ? cB0 : cA0, &x1 = kh ? cB1 : cA1,
                  &x2 = kh ? cB2 : cA2, &x3 = kh ? cB3 : cA3;
            float &y0 = kh ? cD0 : cC0, &y1 = kh ? cD1 : cC1,
                  &y2 = kh ? cD2 : cC2, &y3 = kh ? cD3 : cC3;
            #pragma unroll
            for (int kk = 0; kk < 2; kk++) {
                int kt = kh * 2 + kk;
                mma16816(x0, x1, x2, x3, ah[kt][0], 0u, ah[kt][1], 0u, bhf[0][kt][0], bhf[0][kt][1]);
                mma16816(y0, y1, y2, y3, ah[kt][0], 0u, ah[kt][1], 0u, bhf[1][kt][0], bhf[1][kt][1]);
                mma16816(x0, x1, x2, x3, al[kt][0], 0u, al[kt][1], 0u, bhf[0][kt][0], bhf[0][kt][1]);
                mma16816(y0, y1, y2, y3, al[kt][0], 0u, al[kt][1], 0u, bhf[1][kt][0], bhf[1][kt][1]);
                mma16816(x0, x1, x2, x3, ah[kt][0], 0u, ah[kt][1], 0u, blf[0][kt][0], blf[0][kt][1]);
                mma16816(y0, y1, y2, y3, ah[kt][0], 0u, ah[kt][1], 0u, blf[1][kt][0], blf[1][kt][1]);
            }
        }
        // lane (grp,tig) holds: p = ntile0 cols {2tig, 2tig+1}, q = ntile1 cols, row=batch grp
        float p0 = cA0 + cB0, p1 = cA1 + cB1;
        float q0 = cC0 + cD0, q1 = cC1 + cD1;

        // ---- in-warp gate gather: i=col tig, f=col 4+tig (ntile0); g,o (ntile1) ----
        const int srcA = (lane & 28) + (tig >> 1);   // same batch row, tile col tig
        const int srcB = srcA + 2;                   // tile col 4+tig
        float s0 = __shfl_sync(0xffffffffu, p0, srcA);
        float s1 = __shfl_sync(0xffffffffu, p1, srcA);
        float s2 = __shfl_sync(0xffffffffu, p0, srcB);
        float s3 = __shfl_sync(0xffffffffu, p1, srcB);
        float t0 = __shfl_sync(0xffffffffu, q0, srcA);
        float t1 = __shfl_sync(0xffffffffu, q1, srcA);
        float t2 = __shfl_sync(0xffffffffu, q0, srcB);
        float t3 = __shfl_sync(0xffffffffu, q1, srcB);
        const bool odd = (tig & 1);
        float iv = odd ? s1 : s0;
        float fv = odd ? s3 : s2;
        float gv = odd ? t1 : t0;
        float ov = odd ? t3 : t2;

        // ---- LSTM cell update, write h to next buffer ----
        if (act) {
            iv += gi; fv += gf; gv += gg; ov += go;
            c = sigm(fv) * c + sigm(iv) * tanhap(gv);
            float h = sigm(ov) * tanhap(c);
            __half hh = __float2half_rn(h);
            sm->hhi[cur ^ 1][j][hd] = hh;
            sm->hlo[cur ^ 1][j][hd] = __float2half_rn(h - __half2float(hh));
            if (step == myg) { sm->gh[j][hd] = h; sm->gc[j][hd] = c; }
            gi = n0; gf = n1; gg = n2; go = n3;
        }
        __syncthreads();
    }
}

__global__ void __launch_bounds__(TPB, 1)
cond_enc_kernel(const int* __restrict__ s1, const int* __restrict__ s2,
                const int* __restrict__ l1, const int* __restrict__ l2,
                const float* __restrict__ Whh1, const float* __restrict__ Whh2,
                const float* __restrict__ Wl1, const float* __restrict__ bl1,
                const float* __restrict__ Wl2, const float* __restrict__ bl2,
                float* __restrict__ out)
{
    __shared__ SmemT sm;
    const int tid  = threadIdx.x;
    const int base = blockIdx.x * NB;
    const int warp = tid >> 5, lane = tid & 31;
    const int grp = lane >> 2, tig = lane & 3;
    const bool act = grp < NB;
    const int j = grp, hd = warp * 4 + tig;
    const int bj = min(base + j, 1023);

    // ---------- sentence1 setup ----------
    for (int i = tid; i < NB * 256; i += TPB) {
        int jj = i >> 8, t = i & 255;
        int b = min(base + jj, 1023);
        sm.sidx[jj][t] = s1[b * 256 + t];
    }
    int myg = 0;
    if (act) {
        myg = l1[bj * 64 + hd];
        sm.hhi[0][j][hd] = __float2half_rn(0.f);
        sm.hlo[0][j][hd] = __float2half_rn(0.f);
    }
    __syncthreads();

    float c = 0.f;
    run_lstm(warp, lane, grp, tig, act, hd, myg, GXT[0], Whh1, &sm, c);

    // ---------- capture gathered state, switch to sentence2 ----------
    float hinit = 0.f;
    if (act) { hinit = sm.gh[j][hd]; c = sm.gc[j][hd]; }
    __syncthreads();
    for (int i = tid; i < NB * 256; i += TPB) {
        int jj = i >> 8, t = i & 255;
        int b = min(base + jj, 1023);
        sm.sidx[jj][t] = s2[b * 256 + t];
    }
    if (act) {
        myg = l2[bj * 64 + hd];
        __half hh = __float2half_rn(hinit);
        sm.hhi[0][j][hd] = hh;
        sm.hlo[0][j][hd] = __float2half_rn(hinit - __half2float(hh));
    }
    __syncthreads();

    run_lstm(warp, lane, grp, tig, act, hd, myg, GXT[1], Whh2, &sm, c);

    // ---------- FC head ----------
    for (int u = tid; u < NB * 128; u += TPB) {
        int jj = u >> 7, f = u & 127;
        const float* w = Wl1 + f * 64;
        float a = bl1[f];
        #pragma unroll
        for (int k = 0; k < 64; k++) a += w[k] * sm.gh[jj][k];
        sm.f1[jj][f] = tanhap(a);
    }
    __syncthreads();
    if (tid < NB * 4) {
        int jj = tid >> 2, o = tid & 3;
        const float* w = Wl2 + o * 128;
        float a = bl2[o];
        #pragma unroll 16
        for (int k = 0; k < 128; k++) a += w[k] * sm.f1[jj][k];
        int b = base + jj;
        if (b < 1024) out[b * 4 + o] = a;
    }
}

extern "C" void kernel_launch(void* const* d_in, const int* in_sizes, int n_in,
                              void* d_out, int out_size)
{
    // 0 s1, 1 s2, 2 s1_len, 3 s2_len, 4 s1_s, 5 s2_s, 6 emb,
    // 7 Wih1, 8 Whh1, 9 bih1, 10 bhh1, 11 Wih2, 12 Whh2, 13 bih2, 14 bhh2,
    // 15 Wl1, 16 bl1, 17 Wl2, 18 bl2
    precompute_gx<<<dim3(PCG, 2), 256>>>(
        (const float*)d_in[6],
        (const float*)d_in[7], (const float*)d_in[9], (const float*)d_in[10],
        (const float*)d_in[11], (const float*)d_in[13], (const float*)d_in[14]);

    cond_enc_kernel<<<GRID, TPB>>>(
        (const int*)d_in[0], (const int*)d_in[1],
        (const int*)d_in[2], (const int*)d_in[3],
        (const float*)d_in[8], (const float*)d_in[12],
        (const float*)d_in[15], (const float*)d_in[16],
        (const float*)d_in[17], (const float*)d_in[18],
        (float*)d_out);
}

// round 9
// speedup vs baseline: 1.0483x; 1.0483x over previous
#include <cuda_runtime.h>
#include <cuda_fp16.h>
#include <cstdint>

// Conditional_encoding: B=1024, T=256, V=32004, D=50, H=64
// Stage 1: GX[layer][v][hd*4+gate] = Wih@emb[v] + bih + bhh (token gate table, L2-resident,
//          TRANSPOSED so the gate phase loads one float4 per thread).
// Stage 2: 147 CTAs x 512 threads, NB=7 (R6 two-phase structure, best so far).
//   Recurrence h@Whh^T on tensor cores, m16n8k16 fp16 hi/lo split (3 passes, fp32-accurate).
//   A-fragments via ldmatrix.x4: tiles = (hhi k0-7, hhi k8-15, hlo k0-7, hlo k8-15),
//   rows = batches 0-6 + zero row 7. 4 ldmatrix/warp/step instead of 16 LDS.

typedef unsigned long long ull;

#define NB   7
#define TPB  512
#define GRID 147
#define VOC  32004

__device__ __align__(16) float GXT[2][(size_t)VOC * 256];

__device__ __forceinline__ ull ffma2(ull a, ull b, ull c) {
    ull d;
    asm("fma.rn.f32x2 %0, %1, %2, %3;" : "=l"(d) : "l"(a), "l"(b), "l"(c));
    return d;
}
__device__ __forceinline__ float lo32(ull v) { return __uint_as_float((unsigned)v); }
__device__ __forceinline__ float hi32(ull v) { return __uint_as_float((unsigned)(v >> 32)); }
__device__ __forceinline__ float tanhap(float x) {
    float y;
    asm("tanh.approx.f32 %0, %1;" : "=f"(y) : "f"(x));
    return y;
}
__device__ __forceinline__ float sigm(float x) { return 0.5f * tanhap(0.5f * x) + 0.5f; }

__device__ __forceinline__ void mma16816(float& c0, float& c1, float& c2, float& c3,
                                         unsigned a0, unsigned a1, unsigned a2, unsigned a3,
                                         unsigned b0, unsigned b1) {
    asm volatile("mma.sync.aligned.m16n8k16.row.col.f32.f16.f16.f32 "
                 "{%0,%1,%2,%3}, {%4,%5,%6,%7}, {%8,%9}, {%0,%1,%2,%3};"
                 : "+f"(c0), "+f"(c1), "+f"(c2), "+f"(c3)
                 : "r"(a0), "r"(a1), "r"(a2), "r"(a3), "r"(b0), "r"(b1));
}
__device__ __forceinline__ void ldmat_x4(unsigned& r0, unsigned& r1, unsigned& r2, unsigned& r3,
                                         uint32_t addr) {
    asm volatile("ldmatrix.sync.aligned.m8n8.x4.shared.b16 {%0,%1,%2,%3}, [%4];"
                 : "=r"(r0), "=r"(r1), "=r"(r2), "=r"(r3) : "r"(addr));
}
__device__ __forceinline__ unsigned h2u(__half2 h) { return *reinterpret_cast<unsigned*>(&h); }
__device__ __forceinline__ uint32_t smem_u32(const void* p) {
    return (uint32_t)__cvta_generic_to_shared(p);
}

// ---------------- stage 1: vocab gate-table precompute (4 tokens / iter) ----------------
#define PCT 4
#define PCI 14
#define PCC (PCT * PCI)
#define PCG ((VOC + PCC - 1) / PCC)

__global__ void __launch_bounds__(256)
precompute_gx(const float* __restrict__ emb,
              const float* __restrict__ Wih1, const float* __restrict__ bih1,
              const float* __restrict__ bhh1,
              const float* __restrict__ Wih2, const float* __restrict__ bih2,
              const float* __restrict__ bhh2)
{
    const int layer = blockIdx.y;
    const float* __restrict__ Wih = layer ? Wih2 : Wih1;
    const float* __restrict__ bi  = layer ? bih2 : bih1;
    const float* __restrict__ bh  = layer ? bhh2 : bhh1;
    float* __restrict__ GX = GXT[layer];

    const int tid = threadIdx.x;               // gate row (gate = tid>>6, hd = tid&63)
    const int sto = (tid & 63) * 4 + (tid >> 6);  // transposed output index
    ull wih[25];
    const ull* wr = reinterpret_cast<const ull*>(Wih + tid * 50);
    #pragma unroll
    for (int k = 0; k < 25; k++) wih[k] = wr[k];
    const float bsum = bi[tid] + bh[tid];

    __shared__ __align__(16) float xb[2][PCT][52];
    const int v0 = blockIdx.x * PCC;
    const int lt = tid / 50, ld = tid % 50;
    const bool lp = tid < PCT * 50;

    if (lp) {
        int v = min(v0 + lt, VOC - 1);
        xb[0][lt][ld] = __ldg(&emb[(size_t)v * 50 + ld]);
    }
    __syncthreads();

    for (int it = 0; it < PCI; it++) {
        const int cur = it & 1;
        const int vb = v0 + it * PCT;
        float pf = 0.f;
        if (lp && it + 1 < PCI) {
            int v = min(vb + PCT + lt, VOC - 1);
            pf = __ldg(&emb[(size_t)v * 50 + ld]);
        }
        ull acc[PCT] = {0ull, 0ull, 0ull, 0ull};
        #pragma unroll
        for (int k = 0; k < 25; k++) {
            #pragma unroll
            for (int t = 0; t < PCT; t++)
                acc[t] = ffma2(wih[k], *reinterpret_cast<const ull*>(&xb[cur][t][k * 2]), acc[t]);
        }
        #pragma unroll
        for (int t = 0; t < PCT; t++) {
            int v = vb + t;
            if (v < VOC) GX[(size_t)v * 256 + sto] = (lo32(acc[t]) + hi32(acc[t])) + bsum;
        }
        if (lp && it + 1 < PCI) xb[cur ^ 1][lt][ld] = pf;
        __syncthreads();
    }
}

// ---------------- stage 2: fused recurrence on tensor cores ----------------
#define HPS 72    // h row stride in halves (144B; 8-row ldmatrix tiles conflict-free)
#define PSS 258

struct SmemT {
    __half hhi[2][8][HPS];     // double-buffered fp16 hi of h; row 7 = zero
    __half hlo[2][8][HPS];     // double-buffered fp16 lo of h; row 7 = zero
    float  psum[NB][PSS];
    float  gh[NB][64];
    float  gc[NB][64];
    float  f1[NB][128];
    int    sidx[NB][256];
};

__device__ __forceinline__ void run_lstm(
    int warp, int lane, int grp, int tig, bool gu, int j, int hd, int myg,
    const float* __restrict__ gx, const float* __restrict__ Whh,
    SmemT* sm, float& c)
{
    // ---- B fragments: row n = warp*16 + nt*8 + grp (same as R6), hi/lo split ----
    unsigned bhf[2][4][2], blf[2][4][2];
    #pragma unroll
    for (int nt = 0; nt < 2; nt++) {
        const int n = warp * 16 + nt * 8 + grp;
        #pragma unroll
        for (int kt = 0; kt < 4; kt++) {
            int k = kt * 16 + tig * 2;
            float2 w0 = *reinterpret_cast<const float2*>(&Whh[n * 64 + k]);
            float2 w1 = *reinterpret_cast<const float2*>(&Whh[n * 64 + k + 8]);
            __half2 h0 = __floats2half2_rn(w0.x, w0.y);
            __half2 h1 = __floats2half2_rn(w1.x, w1.y);
            float2 r0 = __half22float2(h0), r1 = __half22float2(h1);
            __half2 l0 = __floats2half2_rn(w0.x - r0.x, w0.y - r0.y);
            __half2 l1 = __floats2half2_rn(w1.x - r1.x, w1.y - r1.y);
            bhf[nt][kt][0] = h2u(h0); bhf[nt][kt][1] = h2u(h1);
            blf[nt][kt][0] = h2u(l0); blf[nt][kt][1] = h2u(l1);
        }
    }

    // ---- ldmatrix lane addressing: tile = lane>>3, row = lane&7 ----
    // tile0: hhi +0 ; tile1: hhi +8 ; tile2: hlo +0 ; tile3: hlo +8
    const int tt = lane >> 3, rr = lane & 7, co = (tt & 1) * 8;
    const uint32_t aA0 = smem_u32((tt < 2) ? (const void*)&sm->hhi[0][rr][co]
                                           : (const void*)&sm->hlo[0][rr][co]);
    const uint32_t aA1 = smem_u32((tt < 2) ? (const void*)&sm->hhi[1][rr][co]
                                           : (const void*)&sm->hlo[1][rr][co]);

    // gx for step 0 (one float4 per gate-unit thread)
    float4 g4 = make_float4(0.f, 0.f, 0.f, 0.f);
    if (gu)
        g4 = __ldg(reinterpret_cast<const float4*>(gx + (size_t)sm->sidx[j][0] * 256) + hd);

    for (int step = 0; step < 256; step++) {
        const int cur = step & 1;
        const uint32_t ab = cur ? aA1 : aA0;

        // ---- A fragments: 4 ldmatrix.x4 (hi k0-7, hi k8-15, lo k0-7, lo k8-15) ----
        unsigned A0h[4], A2h[4], A0l[4], A2l[4];
        #pragma unroll
        for (int kt = 0; kt < 4; kt++)
            ldmat_x4(A0h[kt], A2h[kt], A0l[kt], A2l[kt], ab + kt * 32);

        // ---- 24 HMMA: 2 ntiles x 2 k-half chains x 3 precision passes ----
        float cA0 = 0.f, cA1 = 0.f, cA2 = 0.f, cA3 = 0.f;
        float cB0 = 0.f, cB1 = 0.f, cB2 = 0.f, cB3 = 0.f;
        float cC0 = 0.f, cC1 = 0.f, cC2 = 0.f, cC3 = 0.f;
        float cD0 = 0.f, cD1 = 0.f, cD2 = 0.f, cD3 = 0.f;
        #pragma unroll
        for (int kh = 0; kh < 2; kh++) {
            float &x0 = kh ? cB0 : cA0, &x1 = kh ? cB1 : cA1,
                  &x2 = kh ? cB2 : cA2, &x3 = kh ? cB3 : cA3;
            float &y0 = kh ? cD0 : cC0, &y1 = kh ? cD1 : cC1,
                  &y2 = kh ? cD2 : cC2, &y3 = kh ? cD3 : cC3;
            #pragma unroll
            for (int kk = 0; kk < 2; kk++) {
                int kt = kh * 2 + kk;
                mma16816(x0, x1, x2, x3, A0h[kt], 0u, A2h[kt], 0u, bhf[0][kt][0], bhf[0][kt][1]);
                mma16816(y0, y1, y2, y3, A0h[kt], 0u, A2h[kt], 0u, bhf[1][kt][0], bhf[1][kt][1]);
                mma16816(x0, x1, x2, x3, A0l[kt], 0u, A2l[kt], 0u, bhf[0][kt][0], bhf[0][kt][1]);
                mma16816(y0, y1, y2, y3, A0l[kt], 0u, A2l[kt], 0u, bhf[1][kt][0], bhf[1][kt][1]);
                mma16816(x0, x1, x2, x3, A0h[kt], 0u, A2h[kt], 0u, blf[0][kt][0], blf[0][kt][1]);
                mma16816(y0, y1, y2, y3, A0h[kt], 0u, A2h[kt], 0u, blf[1][kt][0], blf[1][kt][1]);
            }
        }
        if (grp < NB) {
            int col = warp * 16 + tig * 2;
            *reinterpret_cast<float2*>(&sm->psum[grp][col])     = make_float2(cA0 + cB0, cA1 + cB1);
            *reinterpret_cast<float2*>(&sm->psum[grp][col + 8]) = make_float2(cC0 + cD0, cC1 + cD1);
        }
        __syncthreads();

        // ---- gate phase (threads 0..447), one unit each ----
        if (gu) {
            // prefetch next step's gx early (consumed next iteration)
            float4 n4 = make_float4(0.f, 0.f, 0.f, 0.f);
            if (step < 255)
                n4 = __ldg(reinterpret_cast<const float4*>(
                         gx + (size_t)sm->sidx[j][step + 1] * 256) + hd);

            float gi = sm->psum[j][hd]        + g4.x;
            float gf = sm->psum[j][64 + hd]   + g4.y;
            float gg = sm->psum[j][128 + hd]  + g4.z;
            float go = sm->psum[j][192 + hd]  + g4.w;
            c = sigm(gf) * c + sigm(gi) * tanhap(gg);
            float h = sigm(go) * tanhap(c);
            __half hh = __float2half_rn(h);
            sm->hhi[cur ^ 1][j][hd] = hh;
            sm->hlo[cur ^ 1][j][hd] = __float2half_rn(h - __half2float(hh));
            if (step == myg) { sm->gh[j][hd] = h; sm->gc[j][hd] = c; }
            g4 = n4;
        }
        __syncthreads();
    }
}

__global__ void __launch_bounds__(TPB, 1)
cond_enc_kernel(const int* __restrict__ s1, const int* __restrict__ s2,
                const int* __restrict__ l1, const int* __restrict__ l2,
                const float* __restrict__ Whh1, const float* __restrict__ Whh2,
                const float* __restrict__ Wl1, const float* __restrict__ bl1,
                const float* __restrict__ Wl2, const float* __restrict__ bl2,
                float* __restrict__ out)
{
    __shared__ SmemT sm;
    const int tid  = threadIdx.x;
    const int base = blockIdx.x * NB;
    const int warp = tid >> 5, lane = tid & 31;
    const int grp = lane >> 2, tig = lane & 3;
    const bool gu = tid < NB * 64;
    const int j = tid >> 6, hd = tid & 63;
    const int bj = gu ? min(base + j, 1023) : 0;

    // ---------- zero both h buffers (incl. padding row 7), load sentence1 ----------
    {
        unsigned* hz = reinterpret_cast<unsigned*>(sm.hhi);
        unsigned* lz = reinterpret_cast<unsigned*>(sm.hlo);
        for (int i = tid; i < 2 * 8 * HPS / 2; i += TPB) { hz[i] = 0u; lz[i] = 0u; }
    }
    for (int i = tid; i < NB * 256; i += TPB) {
        int jj = i >> 8, t = i & 255;
        int b = min(base + jj, 1023);
        sm.sidx[jj][t] = s1[b * 256 + t];
    }
    int myg = gu ? l1[bj * 64 + hd] : -1;
    __syncthreads();

    float c = 0.f;
    run_lstm(warp, lane, grp, tig, gu, j, hd, myg, GXT[0], Whh1, &sm, c);

    // ---------- capture gathered state, switch to sentence2 ----------
    float hinit = 0.f;
    if (gu) { hinit = sm.gh[j][hd]; c = sm.gc[j][hd]; }
    __syncthreads();
    for (int i = tid; i < NB * 256; i += TPB) {
        int jj = i >> 8, t = i & 255;
        int b = min(base + jj, 1023);
        sm.sidx[jj][t] = s2[b * 256 + t];
    }
    if (gu) {
        myg = l2[bj * 64 + hd];
        __half hh = __float2half_rn(hinit);
        sm.hhi[0][j][hd] = hh;
        sm.hlo[0][j][hd] = __float2half_rn(hinit - __half2float(hh));
    }
    __syncthreads();

    run_lstm(warp, lane, grp, tig, gu, j, hd, myg, GXT[1], Whh2, &sm, c);

    // ---------- FC head ----------
    for (int u = tid; u < NB * 128; u += TPB) {
        int jj = u >> 7, f = u & 127;
        const float* w = Wl1 + f * 64;
        float a = bl1[f];
        #pragma unroll
        for (int k = 0; k < 64; k++) a += w[k] * sm.gh[jj][k];
        sm.f1[jj][f] = tanhap(a);
    }
    __syncthreads();
    if (tid < NB * 4) {
        int jj = tid >> 2, o = tid & 3;
        const float* w = Wl2 + o * 128;
        float a = bl2[o];
        #pragma unroll 16
        for (int k = 0; k < 128; k++) a += w[k] * sm.f1[jj][k];
        int b = base + jj;
        if (b < 1024) out[b * 4 + o] = a;
    }
}

extern "C" void kernel_launch(void* const* d_in, const int* in_sizes, int n_in,
                              void* d_out, int out_size)
{
    // 0 s1, 1 s2, 2 s1_len, 3 s2_len, 4 s1_s, 5 s2_s, 6 emb,
    // 7 Wih1, 8 Whh1, 9 bih1, 10 bhh1, 11 Wih2, 12 Whh2, 13 bih2, 14 bhh2,
    // 15 Wl1, 16 bl1, 17 Wl2, 18 bl2
    precompute_gx<<<dim3(PCG, 2), 256>>>(
        (const float*)d_in[6],
        (const float*)d_in[7], (const float*)d_in[9], (const float*)d_in[10],
        (const float*)d_in[11], (const float*)d_in[13], (const float*)d_in[14]);

    cond_enc_kernel<<<GRID, TPB>>>(
        (const int*)d_in[0], (const int*)d_in[1],
        (const int*)d_in[2], (const int*)d_in[3],
        (const float*)d_in[8], (const float*)d_in[12],
        (const float*)d_in[15], (const float*)d_in[16],
        (const float*)d_in[17], (const float*)d_in[18],
        (float*)d_out);
}

// round 12
// speedup vs baseline: 1.1783x; 1.1240x over previous
#include <cuda_runtime.h>
#include <cuda_fp16.h>
#include <cstdint>

// Conditional_encoding: B=1024, T=256, V=32004, D=50, H=64
// Stage 1: GX[layer][v][hd*4+gate] = Wih@emb[v] + bih + bhh (token gate table, L2-resident,
//          transposed so the gate phase loads one float4 per thread).
// Stage 2: 147 CTAs x 512 threads, NB=7 (R6 two-phase structure).
//   Recurrence h@Whh^T on tensor cores, m16n8k16 fp16 hi/lo split (3 passes, fp32-accurate).
//   A-fragments via 4x ldmatrix.x4; gx prefetch issued BEFORE the MMA phase (hidden
//   under the HMMA burst) and consumed in the gate phase -- the R6 overlap, restored.

typedef unsigned long long ull;

#define NB   7
#define TPB  512
#define GRID 147
#define VOC  32004

__device__ __align__(16) float GXT[2][(size_t)VOC * 256];

__device__ __forceinline__ ull ffma2(ull a, ull b, ull c) {
    ull d;
    asm("fma.rn.f32x2 %0, %1, %2, %3;" : "=l"(d) : "l"(a), "l"(b), "l"(c));
    return d;
}
__device__ __forceinline__ float lo32(ull v) { return __uint_as_float((unsigned)v); }
__device__ __forceinline__ float hi32(ull v) { return __uint_as_float((unsigned)(v >> 32)); }
__device__ __forceinline__ float tanhap(float x) {
    float y;
    asm("tanh.approx.f32 %0, %1;" : "=f"(y) : "f"(x));
    return y;
}
__device__ __forceinline__ float sigm(float x) { return 0.5f * tanhap(0.5f * x) + 0.5f; }

__device__ __forceinline__ void mma16816(float& c0, float& c1, float& c2, float& c3,
                                         unsigned a0, unsigned a1, unsigned a2, unsigned a3,
                                         unsigned b0, unsigned b1) {
    asm volatile("mma.sync.aligned.m16n8k16.row.col.f32.f16.f16.f32 "
                 "{%0,%1,%2,%3}, {%4,%5,%6,%7}, {%8,%9}, {%0,%1,%2,%3};"
                 : "+f"(c0), "+f"(c1), "+f"(c2), "+f"(c3)
                 : "r"(a0), "r"(a1), "r"(a2), "r"(a3), "r"(b0), "r"(b1));
}
__device__ __forceinline__ void ldmat_x4(unsigned& r0, unsigned& r1, unsigned& r2, unsigned& r3,
                                         uint32_t addr) {
    asm volatile("ldmatrix.sync.aligned.m8n8.x4.shared.b16 {%0,%1,%2,%3}, [%4];"
                 : "=r"(r0), "=r"(r1), "=r"(r2), "=r"(r3) : "r"(addr));
}
__device__ __forceinline__ unsigned h2u(__half2 h) { return *reinterpret_cast<unsigned*>(&h); }
__device__ __forceinline__ uint32_t smem_u32(const void* p) {
    return (uint32_t)__cvta_generic_to_shared(p);
}

// ---------------- stage 1: vocab gate-table precompute (4 tokens / iter) ----------------
#define PCT 4
#define PCI 14
#define PCC (PCT * PCI)
#define PCG ((VOC + PCC - 1) / PCC)

__global__ void __launch_bounds__(256)
precompute_gx(const float* __restrict__ emb,
              const float* __restrict__ Wih1, const float* __restrict__ bih1,
              const float* __restrict__ bhh1,
              const float* __restrict__ Wih2, const float* __restrict__ bih2,
              const float* __restrict__ bhh2)
{
    const int layer = blockIdx.y;
    const float* __restrict__ Wih = layer ? Wih2 : Wih1;
    const float* __restrict__ bi  = layer ? bih2 : bih1;
    const float* __restrict__ bh  = layer ? bhh2 : bhh1;
    float* __restrict__ GX = GXT[layer];

    const int tid = threadIdx.x;                  // gate row (gate = tid>>6, hd = tid&63)
    const int sto = (tid & 63) * 4 + (tid >> 6);  // transposed output index
    ull wih[25];
    const ull* wr = reinterpret_cast<const ull*>(Wih + tid * 50);
    #pragma unroll
    for (int k = 0; k < 25; k++) wih[k] = wr[k];
    const float bsum = bi[tid] + bh[tid];

    __shared__ __align__(16) float xb[2][PCT][52];
    const int v0 = blockIdx.x * PCC;
    const int lt = tid / 50, ld = tid % 50;
    const bool lp = tid < PCT * 50;

    if (lp) {
        int v = min(v0 + lt, VOC - 1);
        xb[0][lt][ld] = __ldg(&emb[(size_t)v * 50 + ld]);
    }
    __syncthreads();

    for (int it = 0; it < PCI; it++) {
        const int cur = it & 1;
        const int vb = v0 + it * PCT;
        float pf = 0.f;
        if (lp && it + 1 < PCI) {
            int v = min(vb + PCT + lt, VOC - 1);
            pf = __ldg(&emb[(size_t)v * 50 + ld]);
        }
        ull acc[PCT] = {0ull, 0ull, 0ull, 0ull};
        #pragma unroll
        for (int k = 0; k < 25; k++) {
            #pragma unroll
            for (int t = 0; t < PCT; t++)
                acc[t] = ffma2(wih[k], *reinterpret_cast<const ull*>(&xb[cur][t][k * 2]), acc[t]);
        }
        #pragma unroll
        for (int t = 0; t < PCT; t++) {
            int v = vb + t;
            if (v < VOC) GX[(size_t)v * 256 + sto] = (lo32(acc[t]) + hi32(acc[t])) + bsum;
        }
        if (lp && it + 1 < PCI) xb[cur ^ 1][lt][ld] = pf;
        __syncthreads();
    }
}

// ---------------- stage 2: fused recurrence on tensor cores ----------------
#define HPS 72    // h row stride in halves (144B; 8-row ldmatrix tiles conflict-free)
#define PSS 258

struct SmemT {
    __half hhi[2][8][HPS];     // double-buffered fp16 hi of h; row 7 = zero
    __half hlo[2][8][HPS];     // double-buffered fp16 lo of h; row 7 = zero
    float  psum[NB][PSS];
    float  gh[NB][64];
    float  gc[NB][64];
    float  f1[NB][128];
    int    sidx[NB][256];
};

__device__ __forceinline__ void run_lstm(
    int warp, int lane, int grp, int tig, bool gu, int j, int hd, int myg,
    const float* __restrict__ gx, const float* __restrict__ Whh,
    SmemT* sm, float& c)
{
    // ---- B fragments: row n = warp*16 + nt*8 + grp, hi/lo split ----
    unsigned bhf[2][4][2], blf[2][4][2];
    #pragma unroll
    for (int nt = 0; nt < 2; nt++) {
        const int n = warp * 16 + nt * 8 + grp;
        #pragma unroll
        for (int kt = 0; kt < 4; kt++) {
            int k = kt * 16 + tig * 2;
            float2 w0 = *reinterpret_cast<const float2*>(&Whh[n * 64 + k]);
            float2 w1 = *reinterpret_cast<const float2*>(&Whh[n * 64 + k + 8]);
            __half2 h0 = __floats2half2_rn(w0.x, w0.y);
            __half2 h1 = __floats2half2_rn(w1.x, w1.y);
            float2 r0 = __half22float2(h0), r1 = __half22float2(h1);
            __half2 l0 = __floats2half2_rn(w0.x - r0.x, w0.y - r0.y);
            __half2 l1 = __floats2half2_rn(w1.x - r1.x, w1.y - r1.y);
            bhf[nt][kt][0] = h2u(h0); bhf[nt][kt][1] = h2u(h1);
            blf[nt][kt][0] = h2u(l0); blf[nt][kt][1] = h2u(l1);
        }
    }

    // ---- ldmatrix lane addressing: tile = lane>>3, row = lane&7 ----
    const int tt = lane >> 3, rr = lane & 7, co = (tt & 1) * 8;
    const uint32_t aA0 = smem_u32((tt < 2) ? (const void*)&sm->hhi[0][rr][co]
                                           : (const void*)&sm->hlo[0][rr][co]);
    const uint32_t aA1 = smem_u32((tt < 2) ? (const void*)&sm->hhi[1][rr][co]
                                           : (const void*)&sm->hlo[1][rr][co]);

    // gx for step 0 (one float4 per gate-unit thread)
    float4 g4 = make_float4(0.f, 0.f, 0.f, 0.f);
    if (gu)
        g4 = __ldg(reinterpret_cast<const float4*>(gx + (size_t)sm->sidx[j][0] * 256) + hd);

    for (int step = 0; step < 256; step++) {
        const int cur = step & 1;
        const uint32_t ab = cur ? aA1 : aA0;

        // ---- prefetch next step's gx BEFORE the MMA burst (latency hidden) ----
        float4 n4 = make_float4(0.f, 0.f, 0.f, 0.f);
        if (gu && step < 255)
            n4 = __ldg(reinterpret_cast<const float4*>(
                     gx + (size_t)sm->sidx[j][step + 1] * 256) + hd);

        // ---- A fragments: 4 ldmatrix.x4 (hi k0-7, hi k8-15, lo k0-7, lo k8-15) ----
        unsigned A0h[4], A2h[4], A0l[4], A2l[4];
        #pragma unroll
        for (int kt = 0; kt < 4; kt++)
            ldmat_x4(A0h[kt], A2h[kt], A0l[kt], A2l[kt], ab + kt * 32);

        // ---- 24 HMMA: 2 ntiles x 2 k-half chains x 3 precision passes ----
        float cA0 = 0.f, cA1 = 0.f, cA2 = 0.f, cA3 = 0.f;
        float cB0 = 0.f, cB1 = 0.f, cB2 = 0.f, cB3 = 0.f;
        float cC0 = 0.f, cC1 = 0.f, cC2 = 0.f, cC3 = 0.f;
        float cD0 = 0.f, cD1 = 0.f, cD2 = 0.f, cD3 = 0.f;
        #pragma unroll
        for (int kh = 0; kh < 2; kh++) {
            float &x0 = kh ? cB0 : cA0, &x1 = kh ? cB1 : cA1,
                  &x2 = kh ? cB2 : cA2, &x3 = kh ? cB3 : cA3;
            float &y0 = kh ? cD0 : cC0, &y1 = kh ? cD1 : cC1,
                  &y2 = kh ? cD2 : cC2, &y3 = kh ? cD3 : cC3;
            #pragma unroll
            for (int kk = 0; kk < 2; kk++) {
                int kt = kh * 2 + kk;
                mma16816(x0, x1, x2, x3, A0h[kt], 0u, A2h[kt], 0u, bhf[0][kt][0], bhf[0][kt][1]);
                mma16816(y0, y1, y2, y3, A0h[kt], 0u, A2h[kt], 0u, bhf[1][kt][0], bhf[1][kt][1]);
                mma16816(x0, x1, x2, x3, A0l[kt], 0u, A2l[kt], 0u, bhf[0][kt][0], bhf[0][kt][1]);
                mma16816(y0, y1, y2, y3, A0l[kt], 0u, A2l[kt], 0u, bhf[1][kt][0], bhf[1][kt][1]);
                mma16816(x0, x1, x2, x3, A0h[kt], 0u, A2h[kt], 0u, blf[0][kt][0], blf[0][kt][1]);
                mma16816(y0, y1, y2, y3, A0h[kt], 0u, A2h[kt], 0u, blf[1][kt][0], blf[1][kt][1]);
            }
        }
        if (grp < NB) {
            int col = warp * 16 + tig * 2;
            *reinterpret_cast<float2*>(&sm->psum[grp][col])     = make_float2(cA0 + cB0, cA1 + cB1);
            *reinterpret_cast<float2*>(&sm->psum[grp][col + 8]) = make_float2(cC0 + cD0, cC1 + cD1);
        }
        __syncthreads();

        // ---- gate phase (threads 0..447), one unit each ----
        if (gu) {
            float gi = sm->psum[j][hd]        + g4.x;
            float gf = sm->psum[j][64 + hd]   + g4.y;
            float gg = sm->psum[j][128 + hd]  + g4.z;
            float go = sm->psum[j][192 + hd]  + g4.w;
            c = sigm(gf) * c + sigm(gi) * tanhap(gg);
            float h = sigm(go) * tanhap(c);
            __half hh = __float2half_rn(h);
            sm->hhi[cur ^ 1][j][hd] = hh;
            sm->hlo[cur ^ 1][j][hd] = __float2half_rn(h - __half2float(hh));
            if (step == myg) { sm->gh[j][hd] = h; sm->gc[j][hd] = c; }
            g4 = n4;
        }
        __syncthreads();
    }
}

__global__ void __launch_bounds__(TPB, 1)
cond_enc_kernel(const int* __restrict__ s1, const int* __restrict__ s2,
                const int* __restrict__ l1, const int* __restrict__ l2,
                const float* __restrict__ Whh1, const float* __restrict__ Whh2,
                const float* __restrict__ Wl1, const float* __restrict__ bl1,
                const float* __restrict__ Wl2, const float* __restrict__ bl2,
                float* __restrict__ out)
{
    __shared__ SmemT sm;
    const int tid  = threadIdx.x;
    const int base = blockIdx.x * NB;
    const int warp = tid >> 5, lane = tid & 31;
    const int grp = lane >> 2, tig = lane & 3;
    const bool gu = tid < NB * 64;
    const int j = tid >> 6, hd = tid & 63;
    const int bj = gu ? min(base + j, 1023) : 0;

    // ---------- zero both h buffers (incl. padding row 7), load sentence1 ----------
    {
        unsigned* hz = reinterpret_cast<unsigned*>(sm.hhi);
        unsigned* lz = reinterpret_cast<unsigned*>(sm.hlo);
        for (int i = tid; i < 2 * 8 * HPS / 2; i += TPB) { hz[i] = 0u; lz[i] = 0u; }
    }
    for (int i = tid; i < NB * 256; i += TPB) {
        int jj = i >> 8, t = i & 255;
        int b = min(base + jj, 1023);
        sm.sidx[jj][t] = s1[b * 256 + t];
    }
    int myg = gu ? l1[bj * 64 + hd] : -1;
    __syncthreads();

    float c = 0.f;
    run_lstm(warp, lane, grp, tig, gu, j, hd, myg, GXT[0], Whh1, &sm, c);

    // ---------- capture gathered state, switch to sentence2 ----------
    float hinit = 0.f;
    if (gu) { hinit = sm.gh[j][hd]; c = sm.gc[j][hd]; }
    __syncthreads();
    for (int i = tid; i < NB * 256; i += TPB) {
        int jj = i >> 8, t = i & 255;
        int b = min(base + jj, 1023);
        sm.sidx[jj][t] = s2[b * 256 + t];
    }
    if (gu) {
        myg = l2[bj * 64 + hd];
        __half hh = __float2half_rn(hinit);
        sm.hhi[0][j][hd] = hh;
        sm.hlo[0][j][hd] = __float2half_rn(hinit - __half2float(hh));
    }
    __syncthreads();

    run_lstm(warp, lane, grp, tig, gu, j, hd, myg, GXT[1], Whh2, &sm, c);

    // ---------- FC head ----------
    for (int u = tid; u < NB * 128; u += TPB) {
        int jj = u >> 7, f = u & 127;
        const float* w = Wl1 + f * 64;
        float a = bl1[f];
        #pragma unroll
        for (int k = 0; k < 64; k++) a += w[k] * sm.gh[jj][k];
        sm.f1[jj][f] = tanhap(a);
    }
    __syncthreads();
    if (tid < NB * 4) {
        int jj = tid >> 2, o = tid & 3;
        const float* w = Wl2 + o * 128;
        float a = bl2[o];
        #pragma unroll 16
        for (int k = 0; k < 128; k++) a += w[k] * sm.f1[jj][k];
        int b = base + jj;
        if (b < 1024) out[b * 4 + o] = a;
    }
}

extern "C" void kernel_launch(void* const* d_in, const int* in_sizes, int n_in,
                              void* d_out, int out_size)
{
    // 0 s1, 1 s2, 2 s1_len, 3 s2_len, 4 s1_s, 5 s2_s, 6 emb,
    // 7 Wih1, 8 Whh1, 9 bih1, 10 bhh1, 11 Wih2, 12 Whh2, 13 bih2, 14 bhh2,
    // 15 Wl1, 16 bl1, 17 Wl2, 18 bl2
    precompute_gx<<<dim3(PCG, 2), 256>>>(
        (const float*)d_in[6],
        (const float*)d_in[7], (const float*)d_in[9], (const float*)d_in[10],
        (const float*)d_in[11], (const float*)d_in[13], (const float*)d_in[14]);

    cond_enc_kernel<<<GRID, TPB>>>(
        (const int*)d_in[0], (const int*)d_in[1],
        (const int*)d_in[2], (const int*)d_in[3],
        (const float*)d_in[8], (const float*)d_in[12],
        (const float*)d_in[15], (const float*)d_in[16],
        (const float*)d_in[17], (const float*)d_in[18],
        (float*)d_out);
}